// round 2
// baseline (speedup 1.0000x reference)
#include <cuda_runtime.h>
#include <cuda_bf16.h>
#include <cstdint>

// upfirdn2d: up=(2,2), down=(1,1), pad=((2,1),(2,1)), 4x4 kernel, gain*up0*up1 = 4
// x: (16, 64, 128, 128) f32  -> out: (16, 64, 255, 255) f32
//
// Derivation (w = kernel[::-1,::-1], pad_lo = 2, lhs_dilation = 2):
//   out[i,j] = 4 * sum_{p,q: (i+p) even, (j+q) even} kernel[3-p][3-q] * x[(i+p-2)/2, (j+q-2)/2]
// Even i=2r : (kernel row 3, input row r-1), (kernel row 1, input row r)
// Odd  i=2r+1: (kernel row 2, input row r), (kernel row 0, input row r+1)
// Identical in columns. Each thread (r,c) emits the 2x2 output block at (2r,2c).
//
// NOTE: image plane stride 255*255 = 65025 is ODD, so no output alignment
// beyond 4B can be assumed anywhere -> scalar stores only.

namespace {

constexpr int H = 128;
constexpr int W = 128;
constexpr int OH = 255;
constexpr int OW = 255;

__global__ void upfirdn_up2_kernel(const float* __restrict__ x,
                                   const float* __restrict__ kern,
                                   float* __restrict__ out) {
    const int c = blockIdx.x * blockDim.x + threadIdx.x;   // input col 0..127
    const int r = blockIdx.y * blockDim.y + threadIdx.y;   // input row 0..127
    const int img = blockIdx.z;                            // 0..1023 (N*C)
    if (c >= W || r >= H) return;

    const float* __restrict__ xp = x + (size_t)img * (H * W);
    float* __restrict__ op = out + (size_t)img * (OH * OW);

    // Kernel (16 floats) with gain 4 folded in. Broadcast load.
    float K[4][4];
#pragma unroll
    for (int a = 0; a < 16; a++) K[a >> 2][a & 3] = __ldg(kern + a) * 4.0f;

    // 3x3 input neighborhood with zero boundary
    float v[3][3];
#pragma unroll
    for (int dr = -1; dr <= 1; dr++) {
#pragma unroll
        for (int dc = -1; dc <= 1; dc++) {
            const int rr = r + dr, cc = c + dc;
            v[dr + 1][dc + 1] = (rr >= 0 && rr < H && cc >= 0 && cc < W)
                                    ? __ldg(xp + rr * W + cc)
                                    : 0.0f;
        }
    }

    // 2x2 output block
    const float o00 = K[3][3] * v[0][0] + K[3][1] * v[0][1] + K[1][3] * v[1][0] + K[1][1] * v[1][1];
    const float o01 = K[3][2] * v[0][1] + K[3][0] * v[0][2] + K[1][2] * v[1][1] + K[1][0] * v[1][2];
    const float o10 = K[2][3] * v[1][0] + K[2][1] * v[1][1] + K[0][3] * v[2][0] + K[0][1] * v[2][1];
    const float o11 = K[2][2] * v[1][1] + K[2][0] * v[1][2] + K[0][2] * v[2][1] + K[0][0] * v[2][2];

    const int i0 = 2 * r;
    const int j0 = 2 * c;

    // Scalar stores only (see alignment note above). Adjacent threads' pairs
    // are contiguous, so each pair of STG.32s covers one contiguous 256B span
    // per warp; L2 merges the interleaved sectors.
    {
        float* row = op + (size_t)i0 * OW;
        row[j0] = o00;
        if (j0 + 1 < OW) row[j0 + 1] = o01;
    }
    if (i0 + 1 < OH) {
        float* row = op + (size_t)(i0 + 1) * OW;
        row[j0] = o10;
        if (j0 + 1 < OW) row[j0 + 1] = o11;
    }
}

}  // namespace

extern "C" void kernel_launch(void* const* d_in, const int* in_sizes, int n_in,
                              void* d_out, int out_size) {
    const float* x = (const float*)d_in[0];      // 16*64*128*128
    const float* kern = (const float*)d_in[1];   // 4*4
    float* out = (float*)d_out;                  // 16*64*255*255

    (void)in_sizes; (void)n_in; (void)out_size;

    dim3 block(32, 8, 1);
    dim3 grid(W / 32, H / 8, 16 * 64);
    upfirdn_up2_kernel<<<grid, block>>>(x, kern, out);
}

// round 3
// speedup vs baseline: 1.0197x; 1.0197x over previous
#include <cuda_runtime.h>
#include <cuda_bf16.h>
#include <cstdint>

// upfirdn2d: up=(2,2), down=(1,1), pad=((2,1),(2,1)), 4x4 kernel, gain*up0*up1 = 4
// x: (16, 64, 128, 128) f32  -> out: (16, 64, 255, 255) f32
//
//   out[2r  ][2c  ] = K33*x[r-1][c-1] + K31*x[r-1][c] + K13*x[r][c-1] + K11*x[r][c]
//   out[2r  ][2c+1] = K32*x[r-1][c  ] + K30*x[r-1][c+1] + K12*x[r][c] + K10*x[r][c+1]
//   out[2r+1][2c  ] = K23*x[r  ][c-1] + K21*x[r  ][c] + K03*x[r+1][c-1] + K01*x[r+1][c]
//   out[2r+1][2c+1] = K22*x[r  ][c  ] + K20*x[r  ][c+1] + K02*x[r+1][c] + K00*x[r+1][c+1]
// (Kij = kernel[i][j], output scaled by 4.)
//
// R2 ncu: L1tex 79% / DRAM 38% -> L1-wavefront bound. Fixes here:
//  - coefficients in __constant__ (LDC, zero L1 wavefronts; was 16 bcast LDG/thread)
//  - 4-row strip per thread with rolling registers (18 LDG / 4 px instead of 36)
// Plane stride 255*255 is odd -> no >4B store alignment anywhere; scalar STG only.

namespace {

constexpr int H = 128;
constexpr int W = 128;
constexpr int OH = 255;
constexpr int OW = 255;
constexpr int RPT = 4;  // input rows per thread

}  // namespace

__constant__ float cK[16];

namespace {

__global__ void upfirdn_up2_kernel(const float* __restrict__ x,
                                   float* __restrict__ out) {
    const int c = blockIdx.x * blockDim.x + threadIdx.x;          // input col
    const int r0 = (blockIdx.y * blockDim.y + threadIdx.y) * RPT; // first input row
    const int img = blockIdx.z;

    const float* __restrict__ xp = x + (size_t)img * (H * W);
    float* __restrict__ op = out + (size_t)img * (OH * OW);

    const bool cl_ok = (c > 0);
    const bool cr_ok = (c + 1 < W);

    // rolling registers: row r-1 (p*), row r (u*), row r+1 (n*)
    float pL, pM, pR, uL, uM, uR;

    // load row r0-1
    if (r0 > 0) {
        const float* row = xp + (size_t)(r0 - 1) * W;
        pM = row[c];
        pL = cl_ok ? row[c - 1] : 0.0f;
        pR = cr_ok ? row[c + 1] : 0.0f;
    } else {
        pL = pM = pR = 0.0f;
    }
    // load row r0
    {
        const float* row = xp + (size_t)r0 * W;
        uM = row[c];
        uL = cl_ok ? row[c - 1] : 0.0f;
        uR = cr_ok ? row[c + 1] : 0.0f;
    }

#pragma unroll
    for (int k = 0; k < RPT; k++) {
        const int r = r0 + k;
        float nL, nM, nR;
        if (r + 1 < H) {
            const float* row = xp + (size_t)(r + 1) * W;
            nM = row[c];
            nL = cl_ok ? row[c - 1] : 0.0f;
            nR = cr_ok ? row[c + 1] : 0.0f;
        } else {
            nL = nM = nR = 0.0f;
        }

        const float o00 = cK[15] * pL + cK[13] * pM + cK[7]  * uL + cK[5] * uM;
        const float o01 = cK[14] * pM + cK[12] * pR + cK[6]  * uM + cK[4] * uR;
        const float o10 = cK[11] * uL + cK[9]  * uM + cK[3]  * nL + cK[1] * nM;
        const float o11 = cK[10] * uM + cK[8]  * uR + cK[2]  * nM + cK[0] * nR;

        const int i0 = 2 * r;
        const int j0 = 2 * c;
        {
            float* row = op + (size_t)i0 * OW;
            row[j0] = 4.0f * o00;
            if (j0 + 1 < OW) row[j0 + 1] = 4.0f * o01;
        }
        if (i0 + 1 < OH) {
            float* row = op + (size_t)(i0 + 1) * OW;
            row[j0] = 4.0f * o10;
            if (j0 + 1 < OW) row[j0 + 1] = 4.0f * o11;
        }

        pL = uL; pM = uM; pR = uR;
        uL = nL; uM = nM; uR = nR;
    }
}

}  // namespace

extern "C" void kernel_launch(void* const* d_in, const int* in_sizes, int n_in,
                              void* d_out, int out_size) {
    const float* x = (const float*)d_in[0];      // 16*64*128*128
    const float* kern = (const float*)d_in[1];   // 4*4
    float* out = (float*)d_out;                  // 16*64*255*255

    (void)in_sizes; (void)n_in; (void)out_size;

    // D2D copy node: coefficients into constant memory (graph-capturable).
    cudaMemcpyToSymbolAsync(cK, kern, 16 * sizeof(float), 0,
                            cudaMemcpyDeviceToDevice);

    dim3 block(32, 8, 1);
    dim3 grid(W / 32, H / (8 * RPT), 16 * 64);
    upfirdn_up2_kernel<<<grid, block>>>(x, out);
}

// round 4
// speedup vs baseline: 1.0679x; 1.0472x over previous
#include <cuda_runtime.h>
#include <cuda_bf16.h>
#include <cstdint>

// upfirdn2d: up=(2,2), down=(1,1), pad=((2,1),(2,1)), 4x4 kernel, gain*up0*up1 = 4
// x: (16, 64, 128, 128) f32  -> out: (16, 64, 255, 255) f32
//
//   out[2r  ][2c  ] = K33*x[r-1][c-1] + K31*x[r-1][c] + K13*x[r][c-1] + K11*x[r][c]
//   out[2r  ][2c+1] = K32*x[r-1][c  ] + K30*x[r-1][c+1] + K12*x[r][c] + K10*x[r][c+1]
//   out[2r+1][2c  ] = K23*x[r  ][c-1] + K21*x[r  ][c] + K03*x[r+1][c-1] + K01*x[r+1][c]
//   out[2r+1][2c+1] = K22*x[r  ][c  ] + K20*x[r  ][c+1] + K02*x[r+1][c] + K00*x[r+1][c+1]
//
// R3 ncu: L1 85.5% / DRAM 39% -> L1-bound. This round:
//  - halo columns via __shfl (1 coalesced LDG + tiny 2-lane edge LDG per row,
//    no misaligned full-warp loads)
//  - packed STG.64 stores: float offset parity of out[i0][j0] is (img+i0)
//    (plane stride 65025 odd, 255 odd, j0 even). Per plane one row-parity class
//    is 8B-aligned ("type A": pairs (j0,j0+1)); the other class is aligned at
//    the shifted pairs (j0+1,j0+2) ("type B": store {b, shfl_down(a)} + edges).

namespace {

constexpr int H = 128;
constexpr int W = 128;
constexpr int OH = 255;
constexpr int OW = 255;
constexpr int RPT = 8;  // input rows per thread

__device__ __forceinline__ void load_row(const float* __restrict__ xp, int rr,
                                         int c, int lane,
                                         float& L, float& M, float& R) {
    float m = 0.0f, e = 0.0f;
    if (rr >= 0 && rr < H) {
        const float* row = xp + (size_t)rr * W;
        m = row[c];
        // warp-edge halo: lane 0 needs c-1, lane 31 needs c+1 (one 2-lane LDG)
        int ec = -1;
        if (lane == 0) { if (c > 0) ec = c - 1; }
        else if (lane == 31) { if (c + 1 < W) ec = c + 1; }
        if (ec >= 0) e = row[ec];
    }
    const float l = __shfl_up_sync(0xffffffffu, m, 1);
    const float r = __shfl_down_sync(0xffffffffu, m, 1);
    L = (lane == 0) ? e : l;
    R = (lane == 31) ? e : r;
    M = m;
}

// Store one output row's pair (a at j0, b at j0+1) for the whole warp.
// typeA: (j0,j0+1) is 8B-aligned -> packed STG.64.
// typeB: (j0+1,j0+2) is 8B-aligned -> STG.64{b, a_next} + edge scalars.
__device__ __forceinline__ void store_row(float* __restrict__ row, int j0,
                                          float a, float b, bool typeA, int lane) {
    const float an = __shfl_down_sync(0xffffffffu, a, 1);
    if (typeA) {
        if (j0 + 1 < OW) {
            *reinterpret_cast<float2*>(row + j0) = make_float2(a, b);
        } else {
            row[j0] = a;
        }
    } else {
        if (lane == 0) row[j0] = a;
        if (j0 + 1 < OW) {
            if (lane < 31) {
                *reinterpret_cast<float2*>(row + j0 + 1) = make_float2(b, an);
            } else {
                row[j0 + 1] = b;
            }
        }
    }
}

}  // namespace

__constant__ float cK[16];

namespace {

__global__ void upfirdn_up2_kernel(const float* __restrict__ x,
                                   float* __restrict__ out) {
    const int lane = threadIdx.x;                                   // 0..31
    const int c = blockIdx.x * 32 + lane;                           // input col
    const int r0 = (blockIdx.y * blockDim.y + threadIdx.y) * RPT;   // first row
    const int img = blockIdx.z;

    const float* __restrict__ xp = x + (size_t)img * (H * W);
    float* __restrict__ op = out + (size_t)img * (OH * OW);

    // even output rows are 8B-aligned iff img is even
    const bool evenA = (img & 1) == 0;

    float pL, pM, pR, uL, uM, uR, nL, nM, nR;
    load_row(xp, r0 - 1, c, lane, pL, pM, pR);
    load_row(xp, r0,     c, lane, uL, uM, uR);

    const int j0 = 2 * c;

#pragma unroll
    for (int k = 0; k < RPT; k++) {
        const int r = r0 + k;
        load_row(xp, r + 1, c, lane, nL, nM, nR);

        const float o00 = 4.0f * (cK[15] * pL + cK[13] * pM + cK[7] * uL + cK[5] * uM);
        const float o01 = 4.0f * (cK[14] * pM + cK[12] * pR + cK[6] * uM + cK[4] * uR);
        const float o10 = 4.0f * (cK[11] * uL + cK[9]  * uM + cK[3] * nL + cK[1] * nM);
        const float o11 = 4.0f * (cK[10] * uM + cK[8]  * uR + cK[2] * nM + cK[0] * nR);

        const int i0 = 2 * r;
        store_row(op + (size_t)i0 * OW, j0, o00, o01, evenA, lane);
        if (i0 + 1 < OH) {
            store_row(op + (size_t)(i0 + 1) * OW, j0, o10, o11, !evenA, lane);
        }

        pL = uL; pM = uM; pR = uR;
        uL = nL; uM = nM; uR = nR;
    }
}

}  // namespace

extern "C" void kernel_launch(void* const* d_in, const int* in_sizes, int n_in,
                              void* d_out, int out_size) {
    const float* x = (const float*)d_in[0];      // 16*64*128*128
    const float* kern = (const float*)d_in[1];   // 4*4
    float* out = (float*)d_out;                  // 16*64*255*255

    (void)in_sizes; (void)n_in; (void)out_size;

    cudaMemcpyToSymbolAsync(cK, kern, 16 * sizeof(float), 0,
                            cudaMemcpyDeviceToDevice);

    dim3 block(32, 8, 1);
    dim3 grid(W / 32, H / (8 * RPT), 16 * 64);
    upfirdn_up2_kernel<<<grid, block>>>(x, out);
}

// round 5
// speedup vs baseline: 1.2913x; 1.2092x over previous
#include <cuda_runtime.h>
#include <cuda_bf16.h>
#include <cstdint>

// upfirdn2d: up=(2,2), down=(1,1), pad=((2,1),(2,1)), 4x4 kernel, gain*up0*up1 = 4
// x: (16, 64, 128, 128) f32  -> out: (16, 64, 255, 255) f32
//
//   out[2r  ][2c  ] = K33*x[r-1][c-1] + K31*x[r-1][c] + K13*x[r][c-1] + K11*x[r][c]
//   out[2r  ][2c+1] = K32*x[r-1][c  ] + K30*x[r-1][c+1] + K12*x[r][c] + K10*x[r][c+1]
//   out[2r+1][2c  ] = K23*x[r  ][c-1] + K21*x[r  ][c] + K03*x[r+1][c-1] + K01*x[r+1][c]
//   out[2r+1][2c+1] = K22*x[r  ][c  ] + K20*x[r  ][c+1] + K02*x[r+1][c] + K00*x[r+1][c+1]
//
// R4 ncu: DRAM 43 / L2 39 / L1 46 / issue 55 -> latency-bound, MLP~1.
// This round: batch ALL row loads up front (MLP ~10-12 per thread), then
// shuffles, then compute+store. Streaming stores (.cs) since output is
// write-once. Parity-classed STG.64 stores and __constant__ coeffs kept.

namespace {

constexpr int H = 128;
constexpr int W = 128;
constexpr int OH = 255;
constexpr int OW = 255;
constexpr int RPT = 4;               // input rows per thread
constexpr int NROWS = RPT + 2;       // rows held in registers

__device__ __forceinline__ void stcs2(float* p, float a, float b) {
    float2 v = make_float2(a, b);
    asm volatile("st.global.cs.v2.f32 [%0], {%1, %2};" :: "l"(p), "f"(v.x), "f"(v.y) : "memory");
}
__device__ __forceinline__ void stcs1(float* p, float a) {
    asm volatile("st.global.cs.f32 [%0], %1;" :: "l"(p), "f"(a) : "memory");
}

// Store one output row's pair (a at j0, b at j0+1) for the whole warp.
// typeA: (j0,j0+1) 8B-aligned -> packed STG.64.
// typeB: (j0+1,j0+2) 8B-aligned -> STG.64{b, a_next} + edge scalars.
__device__ __forceinline__ void store_row(float* __restrict__ row, int j0,
                                          float a, float b, bool typeA, int lane) {
    const float an = __shfl_down_sync(0xffffffffu, a, 1);
    if (typeA) {
        if (j0 + 1 < OW) stcs2(row + j0, a, b);
        else             stcs1(row + j0, a);
    } else {
        if (lane == 0) stcs1(row + j0, a);
        if (j0 + 1 < OW) {
            if (lane < 31) stcs2(row + j0 + 1, b, an);
            else           stcs1(row + j0 + 1, b);
        }
    }
}

}  // namespace

__constant__ float cK[16];

namespace {

__global__ __launch_bounds__(256) void upfirdn_up2_kernel(
        const float* __restrict__ x, float* __restrict__ out) {
    const int lane = threadIdx.x;                                    // 0..31
    const int c = blockIdx.x * 32 + lane;                            // input col
    const int r0 = (blockIdx.y * blockDim.y + threadIdx.y) * RPT;    // first row
    const int img = blockIdx.z;

    const float* __restrict__ xp = x + (size_t)img * (H * W);
    float* __restrict__ op = out + (size_t)img * (OH * OW);

    const bool evenA = (img & 1) == 0;  // even output rows 8B-aligned iff img even

    // ---- Phase 1: batch all loads (independent LDGs -> high MLP) ----
    float M[NROWS], E[NROWS];
#pragma unroll
    for (int i = 0; i < NROWS; i++) {
        const int rr = r0 - 1 + i;
        float m = 0.0f, e = 0.0f;
        if (rr >= 0 && rr < H) {
            const float* row = xp + (size_t)rr * W;
            m = __ldg(row + c);
            int ec = -1;
            if (lane == 0)       { if (c > 0)     ec = c - 1; }
            else if (lane == 31) { if (c + 1 < W) ec = c + 1; }
            if (ec >= 0) e = __ldg(row + ec);
        }
        M[i] = m; E[i] = e;
    }

    // ---- Phase 2: halo via shuffles ----
    float L[NROWS], R[NROWS];
#pragma unroll
    for (int i = 0; i < NROWS; i++) {
        const float l = __shfl_up_sync(0xffffffffu, M[i], 1);
        const float r = __shfl_down_sync(0xffffffffu, M[i], 1);
        L[i] = (lane == 0) ? E[i] : l;
        R[i] = (lane == 31) ? E[i] : r;
    }

    // ---- Phase 3: compute + store ----
    const int j0 = 2 * c;
#pragma unroll
    for (int k = 0; k < RPT; k++) {
        const int r = r0 + k;
        // rows: p = k (r-1), u = k+1 (r), n = k+2 (r+1)
        const float o00 = 4.0f * (cK[15] * L[k]   + cK[13] * M[k]   + cK[7] * L[k+1] + cK[5] * M[k+1]);
        const float o01 = 4.0f * (cK[14] * M[k]   + cK[12] * R[k]   + cK[6] * M[k+1] + cK[4] * R[k+1]);
        const float o10 = 4.0f * (cK[11] * L[k+1] + cK[9]  * M[k+1] + cK[3] * L[k+2] + cK[1] * M[k+2]);
        const float o11 = 4.0f * (cK[10] * M[k+1] + cK[8]  * R[k+1] + cK[2] * M[k+2] + cK[0] * R[k+2]);

        const int i0 = 2 * r;
        store_row(op + (size_t)i0 * OW, j0, o00, o01, evenA, lane);
        if (i0 + 1 < OH) {
            store_row(op + (size_t)(i0 + 1) * OW, j0, o10, o11, !evenA, lane);
        }
    }
}

}  // namespace

extern "C" void kernel_launch(void* const* d_in, const int* in_sizes, int n_in,
                              void* d_out, int out_size) {
    const float* x = (const float*)d_in[0];      // 16*64*128*128
    const float* kern = (const float*)d_in[1];   // 4*4
    float* out = (float*)d_out;                  // 16*64*255*255

    (void)in_sizes; (void)n_in; (void)out_size;

    cudaMemcpyToSymbolAsync(cK, kern, 16 * sizeof(float), 0,
                            cudaMemcpyDeviceToDevice);

    dim3 block(32, 8, 1);
    dim3 grid(W / 32, H / (8 * RPT), 16 * 64);   // (4, 4, 1024) = 16384 blocks
    upfirdn_up2_kernel<<<grid, block>>>(x, out);
}